// round 1
// baseline (speedup 1.0000x reference)
#include <cuda_runtime.h>

// Problem constants (fixed by the reference).
constexpr int Bn = 2;
constexpr int Np = 20000;
constexpr int R  = Bn * Np;       // 40000 point rows

// Scratch (allocation-free rule: __device__ globals).
__device__ float g_h0 [R * 64];    // leaky(inp @ W_init^T + b)        [R,64]
__device__ float g_x1 [R * 128];   // [t1_mean | fn1_mean]             [R,128]
__device__ float g_t2m[R * 128];   // mean_k leaky(geom @ W_l2^T + b)  [R,128]
__device__ float g_x2 [R * 256];   // [t2_mean | fn2_mean]             [R,256]

__device__ __forceinline__ float leaky(float x) { return x > 0.f ? x : 0.1f * x; }

// ---------------------------------------------------------------------------
// k_init: g_h0 = leaky(inp @ W_init^T + b_init).  M=R, N=64, K=256.
// Tile: 64 rows x 64 cols per CTA, BK=32, 256 threads, 4x4 per thread.
// ---------------------------------------------------------------------------
__global__ __launch_bounds__(256) void k_init(const float* __restrict__ A,
                                              const float* __restrict__ W,
                                              const float* __restrict__ bias) {
    __shared__ float As[64][32];
    __shared__ float Ws[64][33];   // +1 pad -> conflict-free strided reads
    const int tid = threadIdx.x;
    const int rowBase = blockIdx.x * 64;
    const int tm = tid >> 4;   // 0..15 (4 rows each)
    const int tn = tid & 15;   // 0..15 (cols tn + 16j)

    float acc[4][4] = {};
    for (int kc = 0; kc < 256; kc += 32) {
        __syncthreads();
        #pragma unroll
        for (int t = tid; t < 512; t += 256) {      // 64x32 A tile (float4)
            int r = t >> 3, c = t & 7;
            float4 v = *(const float4*)(A + (size_t)(rowBase + r) * 256 + kc + c * 4);
            *(float4*)&As[r][c * 4] = v;
        }
        #pragma unroll
        for (int t = tid; t < 512; t += 256) {      // 64x32 W tile
            int n = t >> 3, c = t & 7;
            float4 v = *(const float4*)(W + (size_t)n * 256 + kc + c * 4);
            Ws[n][c * 4 + 0] = v.x; Ws[n][c * 4 + 1] = v.y;
            Ws[n][c * 4 + 2] = v.z; Ws[n][c * 4 + 3] = v.w;
        }
        __syncthreads();
        #pragma unroll 8
        for (int k = 0; k < 32; k++) {
            float a[4], w[4];
            #pragma unroll
            for (int i = 0; i < 4; i++) a[i] = As[tm * 4 + i][k];
            #pragma unroll
            for (int j = 0; j < 4; j++) w[j] = Ws[tn + 16 * j][k];
            #pragma unroll
            for (int i = 0; i < 4; i++)
                #pragma unroll
                for (int j = 0; j < 4; j++)
                    acc[i][j] = fmaf(a[i], w[j], acc[i][j]);
        }
    }
    #pragma unroll
    for (int j = 0; j < 4; j++) {
        float b = bias[tn + 16 * j];
        #pragma unroll
        for (int i = 0; i < 4; i++) {
            size_t r = (size_t)(rowBase + tm * 4 + i);
            g_h0[r * 64 + tn + 16 * j] = leaky(acc[i][j] + b);
        }
    }
}

// ---------------------------------------------------------------------------
// k_geom: per row, t1_mean = mean_k leaky(geom_k @ W_l1^T + b_l1)  (64)
//                  t2_mean = mean_k leaky(geom_k @ W_l2^T + b_l2)  (128)
// leaky applied per-k BEFORE the mean (nonlinear, no shortcut).
// leaky(d) == 0.55*d + 0.45*|d|  -> 2 FMAs, branch-free.
// ---------------------------------------------------------------------------
__global__ __launch_bounds__(256) void k_geom(const float* __restrict__ G,
                                              const float* __restrict__ Wl1,
                                              const float* __restrict__ bl1,
                                              const float* __restrict__ Wl2,
                                              const float* __restrict__ bl2) {
    __shared__ float sg[64][64];       // 64 rows x (16 neighbors * 4)
    __shared__ float sW[192][4];       // [W_l1 ; W_l2]
    __shared__ float sb[192];
    const int tid = threadIdx.x;
    const int rowBase = blockIdx.x * 64;

    for (int t = tid; t < 1024; t += 256) {    // 64*16 float4
        int r = t >> 4, c = t & 15;
        *(float4*)&sg[r][c * 4] = *(const float4*)(G + (size_t)(rowBase + r) * 64 + c * 4);
    }
    if (tid < 64) {
        #pragma unroll
        for (int j = 0; j < 4; j++) sW[tid][j] = Wl1[tid * 4 + j];
        sb[tid] = bl1[tid];
    } else if (tid < 192) {
        int o = tid - 64;
        #pragma unroll
        for (int j = 0; j < 4; j++) sW[tid][j] = Wl2[o * 4 + j];
        sb[tid] = bl2[o];
    }
    __syncthreads();

    // 64 rows x 24 groups of 8 outputs (192 combined outs) = 1536 items
    for (int it = tid; it < 64 * 24; it += 256) {
        int row = it / 24;
        int ob  = (it - row * 24) * 8;
        float w0[8], w1[8], w2[8], w3[8], bb[8];
        #pragma unroll
        for (int o = 0; o < 8; o++) {
            w0[o] = sW[ob + o][0]; w1[o] = sW[ob + o][1];
            w2[o] = sW[ob + o][2]; w3[o] = sW[ob + o][3];
            bb[o] = sb[ob + o];
        }
        float acc[8] = {};
        #pragma unroll
        for (int k = 0; k < 16; k++) {
            float4 g = *(const float4*)&sg[row][k * 4];
            #pragma unroll
            for (int o = 0; o < 8; o++) {
                float d = fmaf(g.x, w0[o], fmaf(g.y, w1[o],
                          fmaf(g.z, w2[o], fmaf(g.w, w3[o], bb[o]))));
                acc[o] = fmaf(0.45f, fabsf(d), fmaf(0.55f, d, acc[o]));
            }
        }
        size_t gr = (size_t)(rowBase + row);
        #pragma unroll
        for (int o = 0; o < 8; o++) {
            float v = acc[o] * 0.0625f;
            int oo = ob + o;
            if (oo < 64) g_x1 [gr * 128 + oo]      = v;   // t1 part of x1
            else         g_t2m[gr * 128 + oo - 64] = v;   // t2 mean
        }
    }
}

// ---------------------------------------------------------------------------
// k_gather1: x1[r,64:128] = mean_k h0[batch(r), idx[r,k], :64]
// one warp per point; lane owns 2 columns (float2) -> coalesced 256B row reads
// ---------------------------------------------------------------------------
__global__ __launch_bounds__(256) void k_gather1(const int* __restrict__ idx) {
    int row  = blockIdx.x * 8 + (threadIdx.x >> 5);
    int lane = threadIdx.x & 31;
    if (row >= R) return;
    const int* ip = idx + (size_t)row * 16;
    const float* base = g_h0 + (size_t)(row / Np) * Np * 64 + lane * 2;
    float ax = 0.f, ay = 0.f;
    #pragma unroll
    for (int k = 0; k < 16; k++) {
        int s = ip[k];
        float2 v = *(const float2*)(base + (size_t)s * 64);
        ax += v.x; ay += v.y;
    }
    *(float2*)(g_x1 + (size_t)row * 128 + 64 + lane * 2) =
        make_float2(ax * 0.0625f, ay * 0.0625f);
}

// ---------------------------------------------------------------------------
// k_gather2: x2[r] = [ t2m[r] | mean_k x1[batch(r), idx[r,k], :128] ]
// one warp per point; lane owns 4 columns (float4) -> coalesced 512B row reads
// ---------------------------------------------------------------------------
__global__ __launch_bounds__(256) void k_gather2(const int* __restrict__ idx) {
    int row  = blockIdx.x * 8 + (threadIdx.x >> 5);
    int lane = threadIdx.x & 31;
    if (row >= R) return;
    const int* ip = idx + (size_t)row * 16;
    const float* base = g_x1 + (size_t)(row / Np) * Np * 128 + lane * 4;
    float a0 = 0.f, a1 = 0.f, a2 = 0.f, a3 = 0.f;
    #pragma unroll
    for (int k = 0; k < 16; k++) {
        int s = ip[k];
        float4 v = *(const float4*)(base + (size_t)s * 128);
        a0 += v.x; a1 += v.y; a2 += v.z; a3 += v.w;
    }
    float4 t = *(const float4*)(g_t2m + (size_t)row * 128 + lane * 4);
    *(float4*)(g_x2 + (size_t)row * 256 + lane * 4) = t;
    *(float4*)(g_x2 + (size_t)row * 256 + 128 + lane * 4) =
        make_float4(a0 * 0.0625f, a1 * 0.0625f, a2 * 0.0625f, a3 * 0.0625f);
}

// ---------------------------------------------------------------------------
// k_final: out = leaky(x2 @ Wf^T + bf) + leaky(inp @ Wi^T + bi)
// M=R, N=256, K=256, twice. Tile 64x256 per CTA, BK=32, 512 threads,
// thread tile 4 rows x 8 cols (cols strided by 32 for conflict-free smem).
// Ws padded to 33 so gmem loads stay coalesced AND strided reads stay
// conflict-free (bank = n + 4c + i, all distinct within a warp).
// ---------------------------------------------------------------------------
__global__ __launch_bounds__(512) void k_final(const float* __restrict__ inp,
                                               const float* __restrict__ Wf,
                                               const float* __restrict__ bf,
                                               const float* __restrict__ Wd,
                                               const float* __restrict__ bd,
                                               float* __restrict__ out) {
    __shared__ float As[64][32];
    __shared__ float Ws[256][33];
    const int tid = threadIdx.x;
    const int rowBase = blockIdx.x * 64;
    const int tm = tid >> 5;   // 0..15 (warp-uniform -> As reads are broadcasts)
    const int tn = tid & 31;   // 0..31

    float res[4][8];
    #pragma unroll 1
    for (int phase = 0; phase < 2; phase++) {
        const float* A    = phase ? inp : g_x2;
        const float* W    = phase ? Wd  : Wf;
        const float* bias = phase ? bd  : bf;
        float acc[4][8] = {};
        for (int kc = 0; kc < 256; kc += 32) {
            __syncthreads();
            {   // 64x32 A tile, one float4 per thread, coalesced
                int r = tid >> 3, c = tid & 7;
                float4 v = *(const float4*)(A + (size_t)(rowBase + r) * 256 + kc + c * 4);
                *(float4*)&As[r][c * 4] = v;
            }
            #pragma unroll
            for (int t = tid; t < 2048; t += 512) {  // 256x32 W tile
                int n = t >> 3, c = t & 7;
                float4 v = *(const float4*)(W + (size_t)n * 256 + kc + c * 4);
                Ws[n][c * 4 + 0] = v.x; Ws[n][c * 4 + 1] = v.y;
                Ws[n][c * 4 + 2] = v.z; Ws[n][c * 4 + 3] = v.w;
            }
            __syncthreads();
            #pragma unroll 4
            for (int k = 0; k < 32; k++) {
                float a[4], w[8];
                #pragma unroll
                for (int j = 0; j < 8; j++) w[j] = Ws[tn + 32 * j][k];
                #pragma unroll
                for (int i = 0; i < 4; i++) a[i] = As[tm * 4 + i][k];
                #pragma unroll
                for (int i = 0; i < 4; i++)
                    #pragma unroll
                    for (int j = 0; j < 8; j++)
                        acc[i][j] = fmaf(a[i], w[j], acc[i][j]);
            }
        }
        if (phase == 0) {
            #pragma unroll
            for (int j = 0; j < 8; j++) {
                float b = bias[tn + 32 * j];
                #pragma unroll
                for (int i = 0; i < 4; i++) res[i][j] = leaky(acc[i][j] + b);
            }
        } else {
            #pragma unroll
            for (int j = 0; j < 8; j++) {
                float b = bias[tn + 32 * j];
                #pragma unroll
                for (int i = 0; i < 4; i++) {
                    size_t r = (size_t)(rowBase + tm * 4 + i);
                    out[r * 256 + tn + 32 * j] = res[i][j] + leaky(acc[i][j] + b);
                }
            }
        }
    }
}

// ---------------------------------------------------------------------------
extern "C" void kernel_launch(void* const* d_in, const int* in_sizes, int n_in,
                              void* d_out, int out_size) {
    const float* inp    = (const float*)d_in[0];   // [2,20000,256]
    const float* geom   = (const float*)d_in[1];   // [2,20000,16,4]
    const int*   idx    = (const int*)  d_in[2];   // [2,20000,16] int32
    const float* W_init = (const float*)d_in[3];
    const float* b_init = (const float*)d_in[4];
    const float* W_l1   = (const float*)d_in[5];
    const float* b_l1   = (const float*)d_in[6];
    const float* W_l2   = (const float*)d_in[7];
    const float* b_l2   = (const float*)d_in[8];
    const float* W_fin  = (const float*)d_in[9];
    const float* b_fin  = (const float*)d_in[10];
    const float* W_id   = (const float*)d_in[11];
    const float* b_id   = (const float*)d_in[12];
    float* out = (float*)d_out;

    k_init   <<<R / 64, 256>>>(inp, W_init, b_init);
    k_geom   <<<R / 64, 256>>>(geom, W_l1, b_l1, W_l2, b_l2);
    k_gather1<<<R / 8,  256>>>(idx);
    k_gather2<<<R / 8,  256>>>(idx);
    k_final  <<<R / 64, 512>>>(inp, W_fin, b_fin, W_id, b_id, out);
}

// round 4
// speedup vs baseline: 1.9230x; 1.9230x over previous
#include <cuda_runtime.h>
#include <cstdint>

// Problem constants (fixed by the reference).
constexpr int Bn = 2;
constexpr int Np = 20000;
constexpr int R  = Bn * Np;       // 40000 point rows

// Scratch (allocation-free rule: __device__ globals).
__device__ float g_h0 [R * 64];    // leaky(inp @ W_init^T + b)        [R,64]
__device__ float g_x1 [R * 128];   // [t1_mean | fn1_mean]             [R,128]
__device__ float g_t2m[R * 128];   // mean_k leaky(geom @ W_l2^T + b)  [R,128]
__device__ float g_x2 [R * 256];   // [t2_mean | fn2_mean]             [R,256]

__device__ __forceinline__ float leaky(float x) { return x > 0.f ? x : 0.1f * x; }

// tf32 helpers (base ISA, sm_80+: no 'a'-gated features).
__device__ __forceinline__ uint32_t f2tf32(float f) {
    uint32_t r;
    asm("cvt.rna.tf32.f32 %0, %1;" : "=r"(r) : "f"(f));
    return r;
}
__device__ __forceinline__ void mma_tf32(float* c, const uint32_t* a, const uint32_t* b) {
    asm volatile(
        "mma.sync.aligned.m16n8k8.row.col.f32.tf32.tf32.f32 "
        "{%0,%1,%2,%3},{%4,%5,%6,%7},{%8,%9},{%0,%1,%2,%3};"
        : "+f"(c[0]), "+f"(c[1]), "+f"(c[2]), "+f"(c[3])
        : "r"(a[0]), "r"(a[1]), "r"(a[2]), "r"(a[3]), "r"(b[0]), "r"(b[1]));
}

// ---------------------------------------------------------------------------
// k_init: g_h0 = leaky(inp @ W_init^T + b_init).  M=R, N=64, K=256.
// Kept exact fp32 (FFMA) to preserve accuracy margin through the LFA chain.
// ---------------------------------------------------------------------------
__global__ __launch_bounds__(256) void k_init(const float* __restrict__ A,
                                              const float* __restrict__ W,
                                              const float* __restrict__ bias) {
    __shared__ float As[64][32];
    __shared__ float Ws[64][33];
    const int tid = threadIdx.x;
    const int rowBase = blockIdx.x * 64;
    const int tm = tid >> 4;
    const int tn = tid & 15;

    float acc[4][4] = {};
    for (int kc = 0; kc < 256; kc += 32) {
        __syncthreads();
        #pragma unroll
        for (int t = tid; t < 512; t += 256) {
            int r = t >> 3, c = t & 7;
            float4 v = *(const float4*)(A + (size_t)(rowBase + r) * 256 + kc + c * 4);
            *(float4*)&As[r][c * 4] = v;
        }
        #pragma unroll
        for (int t = tid; t < 512; t += 256) {
            int n = t >> 3, c = t & 7;
            float4 v = *(const float4*)(W + (size_t)n * 256 + kc + c * 4);
            Ws[n][c * 4 + 0] = v.x; Ws[n][c * 4 + 1] = v.y;
            Ws[n][c * 4 + 2] = v.z; Ws[n][c * 4 + 3] = v.w;
        }
        __syncthreads();
        #pragma unroll 8
        for (int k = 0; k < 32; k++) {
            float a[4], w[4];
            #pragma unroll
            for (int i = 0; i < 4; i++) a[i] = As[tm * 4 + i][k];
            #pragma unroll
            for (int j = 0; j < 4; j++) w[j] = Ws[tn + 16 * j][k];
            #pragma unroll
            for (int i = 0; i < 4; i++)
                #pragma unroll
                for (int j = 0; j < 4; j++)
                    acc[i][j] = fmaf(a[i], w[j], acc[i][j]);
        }
    }
    #pragma unroll
    for (int j = 0; j < 4; j++) {
        float b = bias[tn + 16 * j];
        #pragma unroll
        for (int i = 0; i < 4; i++) {
            size_t r = (size_t)(rowBase + tm * 4 + i);
            g_h0[r * 64 + tn + 16 * j] = leaky(acc[i][j] + b);
        }
    }
}

// ---------------------------------------------------------------------------
// k_geom: t1_mean (64) and t2_mean (128) per row; leaky per-k before mean.
// ---------------------------------------------------------------------------
__global__ __launch_bounds__(256) void k_geom(const float* __restrict__ G,
                                              const float* __restrict__ Wl1,
                                              const float* __restrict__ bl1,
                                              const float* __restrict__ Wl2,
                                              const float* __restrict__ bl2) {
    __shared__ float sg[64][64];
    __shared__ float sW[192][4];
    __shared__ float sb[192];
    const int tid = threadIdx.x;
    const int rowBase = blockIdx.x * 64;

    for (int t = tid; t < 1024; t += 256) {
        int r = t >> 4, c = t & 15;
        *(float4*)&sg[r][c * 4] = *(const float4*)(G + (size_t)(rowBase + r) * 64 + c * 4);
    }
    if (tid < 64) {
        #pragma unroll
        for (int j = 0; j < 4; j++) sW[tid][j] = Wl1[tid * 4 + j];
        sb[tid] = bl1[tid];
    } else if (tid < 192) {
        int o = tid - 64;
        #pragma unroll
        for (int j = 0; j < 4; j++) sW[tid][j] = Wl2[o * 4 + j];
        sb[tid] = bl2[o];
    }
    __syncthreads();

    for (int it = tid; it < 64 * 24; it += 256) {
        int row = it / 24;
        int ob  = (it - row * 24) * 8;
        float w0[8], w1[8], w2[8], w3[8], bb[8];
        #pragma unroll
        for (int o = 0; o < 8; o++) {
            w0[o] = sW[ob + o][0]; w1[o] = sW[ob + o][1];
            w2[o] = sW[ob + o][2]; w3[o] = sW[ob + o][3];
            bb[o] = sb[ob + o];
        }
        float acc[8] = {};
        #pragma unroll
        for (int k = 0; k < 16; k++) {
            float4 g = *(const float4*)&sg[row][k * 4];
            #pragma unroll
            for (int o = 0; o < 8; o++) {
                float d = fmaf(g.x, w0[o], fmaf(g.y, w1[o],
                          fmaf(g.z, w2[o], fmaf(g.w, w3[o], bb[o]))));
                acc[o] = fmaf(0.45f, fabsf(d), fmaf(0.55f, d, acc[o]));
            }
        }
        size_t gr = (size_t)(rowBase + row);
        #pragma unroll
        for (int o = 0; o < 8; o++) {
            float v = acc[o] * 0.0625f;
            int oo = ob + o;
            if (oo < 64) g_x1 [gr * 128 + oo]      = v;
            else         g_t2m[gr * 128 + oo - 64] = v;
        }
    }
}

// ---------------------------------------------------------------------------
// k_gather1: x1[r,64:128] = mean_k h0[batch(r), idx[r,k], :64]
// ---------------------------------------------------------------------------
__global__ __launch_bounds__(256) void k_gather1(const int* __restrict__ idx) {
    int row  = blockIdx.x * 8 + (threadIdx.x >> 5);
    int lane = threadIdx.x & 31;
    if (row >= R) return;
    const int* ip = idx + (size_t)row * 16;
    const float* base = g_h0 + (size_t)(row / Np) * Np * 64 + lane * 2;
    float ax = 0.f, ay = 0.f;
    #pragma unroll
    for (int k = 0; k < 16; k++) {
        int s = ip[k];
        float2 v = *(const float2*)(base + (size_t)s * 64);
        ax += v.x; ay += v.y;
    }
    *(float2*)(g_x1 + (size_t)row * 128 + 64 + lane * 2) =
        make_float2(ax * 0.0625f, ay * 0.0625f);
}

// ---------------------------------------------------------------------------
// k_gather2: x2[r] = [ t2m[r] | mean_k x1[batch(r), idx[r,k], :128] ]
// ---------------------------------------------------------------------------
__global__ __launch_bounds__(256) void k_gather2(const int* __restrict__ idx) {
    int row  = blockIdx.x * 8 + (threadIdx.x >> 5);
    int lane = threadIdx.x & 31;
    if (row >= R) return;
    const int* ip = idx + (size_t)row * 16;
    const float* base = g_x1 + (size_t)(row / Np) * Np * 128 + lane * 4;
    float a0 = 0.f, a1 = 0.f, a2 = 0.f, a3 = 0.f;
    #pragma unroll
    for (int k = 0; k < 16; k++) {
        int s = ip[k];
        float4 v = *(const float4*)(base + (size_t)s * 128);
        a0 += v.x; a1 += v.y; a2 += v.z; a3 += v.w;
    }
    float4 t = *(const float4*)(g_t2m + (size_t)row * 128 + lane * 4);
    *(float4*)(g_x2 + (size_t)row * 256 + lane * 4) = t;
    *(float4*)(g_x2 + (size_t)row * 256 + 128 + lane * 4) =
        make_float4(a0 * 0.0625f, a1 * 0.0625f, a2 * 0.0625f, a3 * 0.0625f);
}

// ---------------------------------------------------------------------------
// k_final_mma: out = leaky(x2 @ Wf^T + bf) + leaky(inp @ Wi^T + bi)
// mma.sync m16n8k8 tf32 (base ISA — tcgen05 is ptxas-rejected at compute_103).
// CTA 64x256, 8 warps as 2(M)x4(N), warp tile 32x64. K chunks of 32.
// SMEM stride 36 floats: fragment LDS banks = 4g+c (all-distinct, conflict
// free), 144B rows keep float4 alignment. cvt.rna in the producer (unbiased).
// Phase 0 writes leaky(...) to out; phase 1 accumulates — same lane owns the
// same (row,col) both phases, so no extra sync/registers.
// ---------------------------------------------------------------------------
__global__ __launch_bounds__(256, 2) void k_final_mma(const float* __restrict__ inp,
                                                      const float* __restrict__ Wf,
                                                      const float* __restrict__ bf,
                                                      const float* __restrict__ Wd,
                                                      const float* __restrict__ bd,
                                                      float* __restrict__ out) {
    __shared__ uint32_t As[64][36];
    __shared__ uint32_t Bs[256][36];
    __shared__ float sbias[512];
    const int tid = threadIdx.x;
    const int l   = tid & 31;
    const int w   = tid >> 5;
    const int g   = l >> 2;       // fragment group row
    const int c   = l & 3;        // fragment group col
    const int wm  = w >> 2;       // 0..1
    const int wn  = w & 3;        // 0..3
    const int rowBase = blockIdx.x * 64;

    for (int t = tid; t < 512; t += 256) sbias[t] = (t < 256) ? bf[t] : bd[t - 256];

    #pragma unroll 1
    for (int phase = 0; phase < 2; phase++) {
        const float* A = phase ? inp : g_x2;
        const float* W = phase ? Wd  : Wf;
        float acc[2][8][4] = {};

        for (int kc = 0; kc < 256; kc += 32) {
            __syncthreads();
            #pragma unroll
            for (int t = tid; t < 512; t += 256) {            // A: 64x32
                int r = t >> 3, c4 = t & 7;
                float4 v = *(const float4*)(A + (size_t)(rowBase + r) * 256 + kc + c4 * 4);
                uint32_t* d = &As[r][c4 * 4];
                d[0] = f2tf32(v.x); d[1] = f2tf32(v.y);
                d[2] = f2tf32(v.z); d[3] = f2tf32(v.w);
            }
            #pragma unroll
            for (int t = tid; t < 2048; t += 256) {           // B: 256x32
                int n = t >> 3, c4 = t & 7;
                float4 v = *(const float4*)(W + (size_t)n * 256 + kc + c4 * 4);
                uint32_t* d = &Bs[n][c4 * 4];
                d[0] = f2tf32(v.x); d[1] = f2tf32(v.y);
                d[2] = f2tf32(v.z); d[3] = f2tf32(v.w);
            }
            __syncthreads();

            #pragma unroll
            for (int ks = 0; ks < 4; ks++) {
                uint32_t af[2][4], bfr[8][2];
                #pragma unroll
                for (int mt = 0; mt < 2; mt++) {
                    int r0 = wm * 32 + mt * 16 + g;
                    af[mt][0] = As[r0    ][ks * 8 + c];
                    af[mt][1] = As[r0 + 8][ks * 8 + c];
                    af[mt][2] = As[r0    ][ks * 8 + c + 4];
                    af[mt][3] = As[r0 + 8][ks * 8 + c + 4];
                }
                #pragma unroll
                for (int nt = 0; nt < 8; nt++) {
                    int n0 = wn * 64 + nt * 8 + g;
                    bfr[nt][0] = Bs[n0][ks * 8 + c];
                    bfr[nt][1] = Bs[n0][ks * 8 + c + 4];
                }
                #pragma unroll
                for (int mt = 0; mt < 2; mt++)
                    #pragma unroll
                    for (int nt = 0; nt < 8; nt++)
                        mma_tf32(acc[mt][nt], af[mt], bfr[nt]);
            }
        }

        // Epilogue
        #pragma unroll
        for (int mt = 0; mt < 2; mt++) {
            size_t r0 = (size_t)(rowBase + wm * 32 + mt * 16 + g);
            #pragma unroll
            for (int nt = 0; nt < 8; nt++) {
                int col = wn * 64 + nt * 8 + c * 2;
                float b0 = sbias[phase * 256 + col];
                float b1 = sbias[phase * 256 + col + 1];
                float* p0 = out + r0 * 256 + col;
                float* p1 = out + (r0 + 8) * 256 + col;
                if (phase == 0) {
                    *(float2*)p0 = make_float2(leaky(acc[mt][nt][0] + b0),
                                               leaky(acc[mt][nt][1] + b1));
                    *(float2*)p1 = make_float2(leaky(acc[mt][nt][2] + b0),
                                               leaky(acc[mt][nt][3] + b1));
                } else {
                    float2 q0 = *(const float2*)p0;
                    float2 q1 = *(const float2*)p1;
                    *(float2*)p0 = make_float2(q0.x + leaky(acc[mt][nt][0] + b0),
                                               q0.y + leaky(acc[mt][nt][1] + b1));
                    *(float2*)p1 = make_float2(q1.x + leaky(acc[mt][nt][2] + b0),
                                               q1.y + leaky(acc[mt][nt][3] + b1));
                }
            }
        }
    }
}

// ---------------------------------------------------------------------------
extern "C" void kernel_launch(void* const* d_in, const int* in_sizes, int n_in,
                              void* d_out, int out_size) {
    const float* inp    = (const float*)d_in[0];   // [2,20000,256]
    const float* geom   = (const float*)d_in[1];   // [2,20000,16,4]
    const int*   idx    = (const int*)  d_in[2];   // [2,20000,16] int32
    const float* W_init = (const float*)d_in[3];
    const float* b_init = (const float*)d_in[4];
    const float* W_l1   = (const float*)d_in[5];
    const float* b_l1   = (const float*)d_in[6];
    const float* W_l2   = (const float*)d_in[7];
    const float* b_l2   = (const float*)d_in[8];
    const float* W_fin  = (const float*)d_in[9];
    const float* b_fin  = (const float*)d_in[10];
    const float* W_id   = (const float*)d_in[11];
    const float* b_id   = (const float*)d_in[12];
    float* out = (float*)d_out;

    k_init     <<<R / 64, 256>>>(inp, W_init, b_init);
    k_geom     <<<R / 64, 256>>>(geom, W_l1, b_l1, W_l2, b_l2);
    k_gather1  <<<R / 8,  256>>>(idx);
    k_gather2  <<<R / 8,  256>>>(idx);
    k_final_mma<<<R / 64, 256>>>(inp, W_fin, b_fin, W_id, b_id, out);
}

// round 5
// speedup vs baseline: 2.3855x; 1.2405x over previous
#include <cuda_runtime.h>
#include <cstdint>
#include <cuda_fp16.h>

// Problem constants (fixed by the reference).
constexpr int Bn = 2;
constexpr int Np = 20000;
constexpr int R  = Bn * Np;       // 40000 point rows

// Scratch (allocation-free rule: __device__ globals).
__device__ float g_h0 [R * 64];    // leaky(inp @ W_init^T + b)        [R,64]
__device__ float g_x1 [R * 128];   // [t1_mean | fn1_mean]             [R,128]
__device__ float g_t2m[R * 128];   // mean_k leaky(geom @ W_l2^T + b)  [R,128]
__device__ float g_x2 [R * 256];   // [t2_mean | fn2_mean]             [R,256]

__device__ __forceinline__ float leaky(float x) { return x > 0.f ? x : 0.1f * x; }

__device__ __forceinline__ uint32_t pack2(float a, float b) {
    __half2 h = __floats2half2_rn(a, b);
    return *reinterpret_cast<uint32_t*>(&h);
}
// m16n8k16 row.col f32 <- f16*f16 + f32 (base ISA, sm_80+).
__device__ __forceinline__ void mma_fp16(float* c, const uint32_t* a, const uint32_t* b) {
    asm volatile(
        "mma.sync.aligned.m16n8k16.row.col.f32.f16.f16.f32 "
        "{%0,%1,%2,%3},{%4,%5,%6,%7},{%8,%9},{%0,%1,%2,%3};"
        : "+f"(c[0]), "+f"(c[1]), "+f"(c[2]), "+f"(c[3])
        : "r"(a[0]), "r"(a[1]), "r"(a[2]), "r"(a[3]), "r"(b[0]), "r"(b[1]));
}

// ---------------------------------------------------------------------------
// k_init_hmma: g_h0 = leaky(inp @ W_init^T + b_init).  M=R, N=64, K=256.
// fp16 HMMA, CTA tile 128x64, 8 warps (4M x 2N), warp tile 32x32.
// Double-buffered SMEM (stride 20 b32 -> conflict-free fragment banks).
// ---------------------------------------------------------------------------
__global__ __launch_bounds__(256, 2) void k_init_hmma(const float* __restrict__ A,
                                                      const float* __restrict__ W,
                                                      const float* __restrict__ bias) {
    __shared__ uint32_t As[2][128][20];
    __shared__ uint32_t Ws[2][64][20];
    __shared__ float sb[64];
    const int tid = threadIdx.x;
    const int l = tid & 31, w = tid >> 5;
    const int g = l >> 2, c = l & 3;
    const int wm = w >> 1, wn = w & 1;
    const int rowBase = blockIdx.x * 128;

    if (tid < 64) sb[tid] = bias[tid];

    float acc[2][4][4] = {};
    float4 ra[4], rw[2];

    // prologue: chunk 0
    #pragma unroll
    for (int i = 0; i < 4; i++) {
        int s = tid + i * 256;
        int r = rowBase + (s >> 3); if (r >= R) r = R - 1;
        ra[i] = *(const float4*)(A + (size_t)r * 256 + ((s & 7) << 2));
    }
    #pragma unroll
    for (int i = 0; i < 2; i++) {
        int s = tid + i * 256;
        rw[i] = *(const float4*)(W + (size_t)(s >> 3) * 256 + ((s & 7) << 2));
    }
    #pragma unroll
    for (int i = 0; i < 4; i++) {
        int s = tid + i * 256, r = s >> 3, c4 = s & 7;
        As[0][r][c4 * 2]     = pack2(ra[i].x, ra[i].y);
        As[0][r][c4 * 2 + 1] = pack2(ra[i].z, ra[i].w);
    }
    #pragma unroll
    for (int i = 0; i < 2; i++) {
        int s = tid + i * 256, r = s >> 3, c4 = s & 7;
        Ws[0][r][c4 * 2]     = pack2(rw[i].x, rw[i].y);
        Ws[0][r][c4 * 2 + 1] = pack2(rw[i].z, rw[i].w);
    }
    __syncthreads();

    #pragma unroll 2
    for (int ch = 0; ch < 8; ch++) {
        const int cur = ch & 1;
        if (ch < 7) {
            int kc = (ch + 1) * 32;
            #pragma unroll
            for (int i = 0; i < 4; i++) {
                int s = tid + i * 256;
                int r = rowBase + (s >> 3); if (r >= R) r = R - 1;
                ra[i] = *(const float4*)(A + (size_t)r * 256 + kc + ((s & 7) << 2));
            }
            #pragma unroll
            for (int i = 0; i < 2; i++) {
                int s = tid + i * 256;
                rw[i] = *(const float4*)(W + (size_t)(s >> 3) * 256 + kc + ((s & 7) << 2));
            }
        }
        #pragma unroll
        for (int ks = 0; ks < 2; ks++) {
            uint32_t af[2][4], bfr[4][2];
            #pragma unroll
            for (int mt = 0; mt < 2; mt++) {
                int r0 = wm * 32 + mt * 16 + g;
                af[mt][0] = As[cur][r0][ks * 8 + c];
                af[mt][1] = As[cur][r0 + 8][ks * 8 + c];
                af[mt][2] = As[cur][r0][ks * 8 + c + 4];
                af[mt][3] = As[cur][r0 + 8][ks * 8 + c + 4];
            }
            #pragma unroll
            for (int nt = 0; nt < 4; nt++) {
                int n0 = wn * 32 + nt * 8 + g;
                bfr[nt][0] = Ws[cur][n0][ks * 8 + c];
                bfr[nt][1] = Ws[cur][n0][ks * 8 + c + 4];
            }
            #pragma unroll
            for (int mt = 0; mt < 2; mt++)
                #pragma unroll
                for (int nt = 0; nt < 4; nt++)
                    mma_fp16(acc[mt][nt], af[mt], bfr[nt]);
        }
        if (ch < 7) {
            #pragma unroll
            for (int i = 0; i < 4; i++) {
                int s = tid + i * 256, r = s >> 3, c4 = s & 7;
                As[cur ^ 1][r][c4 * 2]     = pack2(ra[i].x, ra[i].y);
                As[cur ^ 1][r][c4 * 2 + 1] = pack2(ra[i].z, ra[i].w);
            }
            #pragma unroll
            for (int i = 0; i < 2; i++) {
                int s = tid + i * 256, r = s >> 3, c4 = s & 7;
                Ws[cur ^ 1][r][c4 * 2]     = pack2(rw[i].x, rw[i].y);
                Ws[cur ^ 1][r][c4 * 2 + 1] = pack2(rw[i].z, rw[i].w);
            }
        }
        __syncthreads();
    }

    #pragma unroll
    for (int mt = 0; mt < 2; mt++) {
        int r0 = rowBase + wm * 32 + mt * 16 + g;
        #pragma unroll
        for (int nt = 0; nt < 4; nt++) {
            int col = wn * 32 + nt * 8 + c * 2;
            float b0 = sb[col], b1 = sb[col + 1];
            if (r0 < R)
                *(float2*)(g_h0 + (size_t)r0 * 64 + col) =
                    make_float2(leaky(acc[mt][nt][0] + b0), leaky(acc[mt][nt][1] + b1));
            if (r0 + 8 < R)
                *(float2*)(g_h0 + (size_t)(r0 + 8) * 64 + col) =
                    make_float2(leaky(acc[mt][nt][2] + b0), leaky(acc[mt][nt][3] + b1));
        }
    }
}

// ---------------------------------------------------------------------------
// k_geom: t1_mean (64) and t2_mean (128) per row; leaky per-k before mean.
// ---------------------------------------------------------------------------
__global__ __launch_bounds__(256) void k_geom(const float* __restrict__ G,
                                              const float* __restrict__ Wl1,
                                              const float* __restrict__ bl1,
                                              const float* __restrict__ Wl2,
                                              const float* __restrict__ bl2) {
    __shared__ float sg[64][64];
    __shared__ float sW[192][4];
    __shared__ float sb[192];
    const int tid = threadIdx.x;
    const int rowBase = blockIdx.x * 64;

    for (int t = tid; t < 1024; t += 256) {
        int r = t >> 4, c = t & 15;
        *(float4*)&sg[r][c * 4] = *(const float4*)(G + (size_t)(rowBase + r) * 64 + c * 4);
    }
    if (tid < 64) {
        #pragma unroll
        for (int j = 0; j < 4; j++) sW[tid][j] = Wl1[tid * 4 + j];
        sb[tid] = bl1[tid];
    } else if (tid < 192) {
        int o = tid - 64;
        #pragma unroll
        for (int j = 0; j < 4; j++) sW[tid][j] = Wl2[o * 4 + j];
        sb[tid] = bl2[o];
    }
    __syncthreads();

    for (int it = tid; it < 64 * 24; it += 256) {
        int row = it / 24;
        int ob  = (it - row * 24) * 8;
        float w0[8], w1[8], w2[8], w3[8], bb[8];
        #pragma unroll
        for (int o = 0; o < 8; o++) {
            w0[o] = sW[ob + o][0]; w1[o] = sW[ob + o][1];
            w2[o] = sW[ob + o][2]; w3[o] = sW[ob + o][3];
            bb[o] = sb[ob + o];
        }
        float acc[8] = {};
        #pragma unroll
        for (int k = 0; k < 16; k++) {
            float4 g = *(const float4*)&sg[row][k * 4];
            #pragma unroll
            for (int o = 0; o < 8; o++) {
                float d = fmaf(g.x, w0[o], fmaf(g.y, w1[o],
                          fmaf(g.z, w2[o], fmaf(g.w, w3[o], bb[o]))));
                acc[o] = fmaf(0.45f, fabsf(d), fmaf(0.55f, d, acc[o]));
            }
        }
        size_t gr = (size_t)(rowBase + row);
        #pragma unroll
        for (int o = 0; o < 8; o++) {
            float v = acc[o] * 0.0625f;
            int oo = ob + o;
            if (oo < 64) g_x1 [gr * 128 + oo]      = v;
            else         g_t2m[gr * 128 + oo - 64] = v;
        }
    }
}

// ---------------------------------------------------------------------------
// k_gather1: x1[r,64:128] = mean_k h0[batch(r), idx[r,k], :64]
// ---------------------------------------------------------------------------
__global__ __launch_bounds__(256) void k_gather1(const int* __restrict__ idx) {
    int row  = blockIdx.x * 8 + (threadIdx.x >> 5);
    int lane = threadIdx.x & 31;
    if (row >= R) return;
    const int* ip = idx + (size_t)row * 16;
    const float* base = g_h0 + (size_t)(row / Np) * Np * 64 + lane * 2;
    float ax = 0.f, ay = 0.f;
    #pragma unroll
    for (int k = 0; k < 16; k++) {
        int s = ip[k];
        float2 v = *(const float2*)(base + (size_t)s * 64);
        ax += v.x; ay += v.y;
    }
    *(float2*)(g_x1 + (size_t)row * 128 + 64 + lane * 2) =
        make_float2(ax * 0.0625f, ay * 0.0625f);
}

// ---------------------------------------------------------------------------
// k_gather2: x2[r] = [ t2m[r] | mean_k x1[batch(r), idx[r,k], :128] ]
// ---------------------------------------------------------------------------
__global__ __launch_bounds__(256) void k_gather2(const int* __restrict__ idx) {
    int row  = blockIdx.x * 8 + (threadIdx.x >> 5);
    int lane = threadIdx.x & 31;
    if (row >= R) return;
    const int* ip = idx + (size_t)row * 16;
    const float* base = g_x1 + (size_t)(row / Np) * Np * 128 + lane * 4;
    float a0 = 0.f, a1 = 0.f, a2 = 0.f, a3 = 0.f;
    #pragma unroll
    for (int k = 0; k < 16; k++) {
        int s = ip[k];
        float4 v = *(const float4*)(base + (size_t)s * 128);
        a0 += v.x; a1 += v.y; a2 += v.z; a3 += v.w;
    }
    float4 t = *(const float4*)(g_t2m + (size_t)row * 128 + lane * 4);
    *(float4*)(g_x2 + (size_t)row * 256 + lane * 4) = t;
    *(float4*)(g_x2 + (size_t)row * 256 + 128 + lane * 4) =
        make_float4(a0 * 0.0625f, a1 * 0.0625f, a2 * 0.0625f, a3 * 0.0625f);
}

// ---------------------------------------------------------------------------
// k_final_hmma: out = leaky(x2 @ Wf^T + bf) + leaky(inp @ Wi^T + bi)
// fp16 m16n8k16 HMMA (same 10-bit mantissa as tf32, 2x rate, half the smem
// traffic). CTA tile 128(M) x 128(N), 512 threads = 16 warps (4M x 4N),
// warp tile 32x32. K chunks of 32, double-buffered SMEM with register
// staging (LDG of chunk c+1 issued before the mma block of chunk c).
// SMEM rows stride 20 b32: fragment banks 20g+c all-distinct.
// Phase 0 writes leaky(..) to out; phase 1 reads back and accumulates.
// ---------------------------------------------------------------------------
__global__ __launch_bounds__(512, 1) void k_final_hmma(const float* __restrict__ inp,
                                                       const float* __restrict__ Wf,
                                                       const float* __restrict__ bf,
                                                       const float* __restrict__ Wd,
                                                       const float* __restrict__ bd,
                                                       float* __restrict__ out) {
    __shared__ uint32_t As[2][128][20];
    __shared__ uint32_t Bs[2][128][20];
    __shared__ float sbias[2][128];
    const int tid = threadIdx.x;
    const int l = tid & 31, w = tid >> 5;
    const int g = l >> 2, c = l & 3;
    const int wm = w >> 2, wn = w & 3;
    const int rowBase = (int)(blockIdx.x >> 1) * 128;
    const int colBase = (int)(blockIdx.x & 1) * 128;

    if (tid < 256) {
        int p = tid >> 7, j = tid & 127;
        sbias[p][j] = p ? bd[colBase + j] : bf[colBase + j];
    }

    #pragma unroll 1
    for (int phase = 0; phase < 2; phase++) {
        const float* A = phase ? inp : g_x2;
        const float* W = phase ? Wd : Wf;
        float acc[2][4][4] = {};
        float4 ra[2], rb[2];

        // prologue: chunk 0
        #pragma unroll
        for (int i = 0; i < 2; i++) {
            int s = tid + i * 512;
            int r = rowBase + (s >> 3); if (r >= R) r = R - 1;
            ra[i] = *(const float4*)(A + (size_t)r * 256 + ((s & 7) << 2));
            rb[i] = *(const float4*)(W + (size_t)(colBase + (s >> 3)) * 256 + ((s & 7) << 2));
        }
        #pragma unroll
        for (int i = 0; i < 2; i++) {
            int s = tid + i * 512, r = s >> 3, c4 = s & 7;
            As[0][r][c4 * 2]     = pack2(ra[i].x, ra[i].y);
            As[0][r][c4 * 2 + 1] = pack2(ra[i].z, ra[i].w);
            Bs[0][r][c4 * 2]     = pack2(rb[i].x, rb[i].y);
            Bs[0][r][c4 * 2 + 1] = pack2(rb[i].z, rb[i].w);
        }
        __syncthreads();

        #pragma unroll 2
        for (int ch = 0; ch < 8; ch++) {
            const int cur = ch & 1;
            if (ch < 7) {
                int kc = (ch + 1) * 32;
                #pragma unroll
                for (int i = 0; i < 2; i++) {
                    int s = tid + i * 512;
                    int r = rowBase + (s >> 3); if (r >= R) r = R - 1;
                    ra[i] = *(const float4*)(A + (size_t)r * 256 + kc + ((s & 7) << 2));
                    rb[i] = *(const float4*)(W + (size_t)(colBase + (s >> 3)) * 256 + kc + ((s & 7) << 2));
                }
            }
            #pragma unroll
            for (int ks = 0; ks < 2; ks++) {
                uint32_t af[2][4], bfr[4][2];
                #pragma unroll
                for (int mt = 0; mt < 2; mt++) {
                    int r0 = wm * 32 + mt * 16 + g;
                    af[mt][0] = As[cur][r0][ks * 8 + c];
                    af[mt][1] = As[cur][r0 + 8][ks * 8 + c];
                    af[mt][2] = As[cur][r0][ks * 8 + c + 4];
                    af[mt][3] = As[cur][r0 + 8][ks * 8 + c + 4];
                }
                #pragma unroll
                for (int nt = 0; nt < 4; nt++) {
                    int n0 = wn * 32 + nt * 8 + g;
                    bfr[nt][0] = Bs[cur][n0][ks * 8 + c];
                    bfr[nt][1] = Bs[cur][n0][ks * 8 + c + 4];
                }
                #pragma unroll
                for (int mt = 0; mt < 2; mt++)
                    #pragma unroll
                    for (int nt = 0; nt < 4; nt++)
                        mma_fp16(acc[mt][nt], af[mt], bfr[nt]);
            }
            if (ch < 7) {
                #pragma unroll
                for (int i = 0; i < 2; i++) {
                    int s = tid + i * 512, r = s >> 3, c4 = s & 7;
                    As[cur ^ 1][r][c4 * 2]     = pack2(ra[i].x, ra[i].y);
                    As[cur ^ 1][r][c4 * 2 + 1] = pack2(ra[i].z, ra[i].w);
                    Bs[cur ^ 1][r][c4 * 2]     = pack2(rb[i].x, rb[i].y);
                    Bs[cur ^ 1][r][c4 * 2 + 1] = pack2(rb[i].z, rb[i].w);
                }
            }
            __syncthreads();
        }

        // epilogue
        #pragma unroll
        for (int mt = 0; mt < 2; mt++) {
            int r0 = rowBase + wm * 32 + mt * 16 + g;
            #pragma unroll
            for (int nt = 0; nt < 4; nt++) {
                int lc = wn * 32 + nt * 8 + c * 2;
                int col = colBase + lc;
                float b0 = sbias[phase][lc], b1 = sbias[phase][lc + 1];
                float* p0 = out + (size_t)r0 * 256 + col;
                float* p1 = out + (size_t)(r0 + 8) * 256 + col;
                if (phase == 0) {
                    if (r0 < R)
                        *(float2*)p0 = make_float2(leaky(acc[mt][nt][0] + b0),
                                                   leaky(acc[mt][nt][1] + b1));
                    if (r0 + 8 < R)
                        *(float2*)p1 = make_float2(leaky(acc[mt][nt][2] + b0),
                                                   leaky(acc[mt][nt][3] + b1));
                } else {
                    if (r0 < R) {
                        float2 q = *(const float2*)p0;
                        *(float2*)p0 = make_float2(q.x + leaky(acc[mt][nt][0] + b0),
                                                   q.y + leaky(acc[mt][nt][1] + b1));
                    }
                    if (r0 + 8 < R) {
                        float2 q = *(const float2*)p1;
                        *(float2*)p1 = make_float2(q.x + leaky(acc[mt][nt][2] + b0),
                                                   q.y + leaky(acc[mt][nt][3] + b1));
                    }
                }
            }
        }
    }
}

// ---------------------------------------------------------------------------
extern "C" void kernel_launch(void* const* d_in, const int* in_sizes, int n_in,
                              void* d_out, int out_size) {
    const float* inp    = (const float*)d_in[0];   // [2,20000,256]
    const float* geom   = (const float*)d_in[1];   // [2,20000,16,4]
    const int*   idx    = (const int*)  d_in[2];   // [2,20000,16] int32
    const float* W_init = (const float*)d_in[3];
    const float* b_init = (const float*)d_in[4];
    const float* W_l1   = (const float*)d_in[5];
    const float* b_l1   = (const float*)d_in[6];
    const float* W_l2   = (const float*)d_in[7];
    const float* b_l2   = (const float*)d_in[8];
    const float* W_fin  = (const float*)d_in[9];
    const float* b_fin  = (const float*)d_in[10];
    const float* W_id   = (const float*)d_in[11];
    const float* b_id   = (const float*)d_in[12];
    float* out = (float*)d_out;

    const int rowTiles = (R + 127) / 128;   // 313
    k_init_hmma <<<rowTiles, 256>>>(inp, W_init, b_init);
    k_geom      <<<R / 64, 256>>>(geom, W_l1, b_l1, W_l2, b_l2);
    k_gather1   <<<R / 8,  256>>>(idx);
    k_gather2   <<<R / 8,  256>>>(idx);
    k_final_hmma<<<rowTiles * 2, 512>>>(inp, W_fin, b_fin, W_id, b_id, out);
}